// round 15
// baseline (speedup 1.0000x reference)
#include <cuda_runtime.h>
#include <math.h>

#define T_TOK   8192
#define D_DIM   4096
#define E_EXP   64
#define BM      64
#define BK      32
#define NTHR    256
#define TOPK    8
#define NPANEL  8
#define PANK    512          // k's per panel
#define XROW    68           // k-major xs row: 64 tokens + 4 pad

// packed fp32 FMA: per-half IEEE RN == two scalar FFMAs, bitwise (proven R13/R14)
#define FMA2(acc, a, b) asm("fma.rn.f32x2 %0, %1, %2, %0;" : "+l"(acc) : "l"(a), "l"(b))
#define PACK2(out, v)   asm("mov.b64 %0, {%1, %1};"        : "=l"(out) : "f"(v))

__device__ float g_partial[NPANEL][T_TOK][E_EXP];   // 16 MB scratch (device global)

// ---------------- kernel 1: per-panel partial GEMM ----------------
__global__ __launch_bounds__(NTHR, 2)
void router_panel_kernel(const float* __restrict__ x,   // [T, D]
                         const float* __restrict__ w)   // [D, E]
{
    __shared__ float xs[BK][XROW];          // k-major: xs[k][token]
    __shared__ float ws[BK][E_EXP];

    const int tid   = threadIdx.x;
    const int tx    = tid & 15;             // experts 4tx..4tx+3
    const int ty    = tid >> 4;             // tokens  4ty..4ty+3
    const int row0  = blockIdx.x * BM;
    const int panel = blockIdx.y;
    const int kbase = panel * PANK;

    // one 512-k panel = one serial ascending FFMA2 chain per (token, expert-pair)
    unsigned long long cha2[4][2];
#pragma unroll
    for (int i = 0; i < 4; ++i)
#pragma unroll
        for (int p = 0; p < 2; ++p) cha2[i][p] = 0ull;

    const int sx0 = tid, sx1 = tid + 256;
    const int xm0 = sx0 >> 3, xq0 = sx0 & 7;
    const int xm1 = sx1 >> 3, xq1 = sx1 & 7;
    const int wk0 = tid >> 4;
    const int weq = tid & 15;

    const float* xbase = x + (size_t)row0 * D_DIM + kbase;

    float4 xr0 = *(const float4*)(xbase + xm0 * D_DIM + xq0 * 4);
    float4 xr1 = *(const float4*)(xbase + xm1 * D_DIM + xq1 * 4);
    float4 wr0 = *(const float4*)(w + (size_t)(kbase + wk0)      * E_EXP + weq * 4);
    float4 wr1 = *(const float4*)(w + (size_t)(kbase + wk0 + 16) * E_EXP + weq * 4);

    const int NCHUNK = PANK / BK;   // 16 chunks per panel
    for (int c = 0; c < NCHUNK; ++c) {
        xs[xq0 * 4 + 0][xm0] = xr0.x;
        xs[xq0 * 4 + 1][xm0] = xr0.y;
        xs[xq0 * 4 + 2][xm0] = xr0.z;
        xs[xq0 * 4 + 3][xm0] = xr0.w;
        xs[xq1 * 4 + 0][xm1] = xr1.x;
        xs[xq1 * 4 + 1][xm1] = xr1.y;
        xs[xq1 * 4 + 2][xm1] = xr1.z;
        xs[xq1 * 4 + 3][xm1] = xr1.w;
        *(float4*)&ws[wk0][weq * 4]      = wr0;
        *(float4*)&ws[wk0 + 16][weq * 4] = wr1;
        __syncthreads();

        if (c + 1 < NCHUNK) {
            const int c0 = (c + 1) * BK;
            xr0 = *(const float4*)(xbase + xm0 * D_DIM + c0 + xq0 * 4);
            xr1 = *(const float4*)(xbase + xm1 * D_DIM + c0 + xq1 * 4);
            wr0 = *(const float4*)(w + (size_t)(kbase + c0 + wk0)      * E_EXP + weq * 4);
            wr1 = *(const float4*)(w + (size_t)(kbase + c0 + wk0 + 16) * E_EXP + weq * 4);
        }

        // serial ascending k; 8 FFMA2 + 4 packs per k
#pragma unroll 8
        for (int k = 0; k < BK; ++k) {
            const float4 xt = *(const float4*)&xs[k][ty * 4];
            const ulonglong2 wp = *(const ulonglong2*)&ws[k][tx * 4];
            unsigned long long x0, x1, x2, x3;
            PACK2(x0, xt.x); PACK2(x1, xt.y); PACK2(x2, xt.z); PACK2(x3, xt.w);
            FMA2(cha2[0][0], x0, wp.x); FMA2(cha2[0][1], x0, wp.y);
            FMA2(cha2[1][0], x1, wp.x); FMA2(cha2[1][1], x1, wp.y);
            FMA2(cha2[2][0], x2, wp.x); FMA2(cha2[2][1], x2, wp.y);
            FMA2(cha2[3][0], x3, wp.x); FMA2(cha2[3][1], x3, wp.y);
        }
        __syncthreads();
    }

    // write panel partials: one coalesced STG.128 per token row
#pragma unroll
    for (int i = 0; i < 4; ++i) {
        const int token = row0 + ty * 4 + i;
        float4 v;
        v.x = __uint_as_float((unsigned int)cha2[i][0]);
        v.y = __uint_as_float((unsigned int)(cha2[i][0] >> 32));
        v.z = __uint_as_float((unsigned int)cha2[i][1]);
        v.w = __uint_as_float((unsigned int)(cha2[i][1] >> 32));
        *(float4*)&g_partial[panel][token][tx * 4] = v;
    }
}

// ---------------- kernel 2: ascending panel fold + top-8 + softmax ----------------
__global__ __launch_bounds__(NTHR, 4)
void router_fold_kernel(float* __restrict__ out, int out_size)
{
    __shared__ float logits[BM][XROW];

    const int tid  = threadIdx.x;
    const int row0 = blockIdx.x * BM;

    // coalesced fold: 64 tokens x 64 experts = 1024 float4 slots
    const size_t blk_off = (size_t)row0 * E_EXP;
    const size_t pstride = (size_t)T_TOK * E_EXP;
    const float* base = &g_partial[0][0][0] + blk_off;

#pragma unroll
    for (int s = 0; s < 4; ++s) {
        const int slot = tid + s * NTHR;            // 0..1023
        float4 acc = *(const float4*)(base + (size_t)slot * 4);
        // ascending panel fold — bitwise identical to tot += cha in c-order
#pragma unroll
        for (int p = 1; p < NPANEL; ++p) {
            const float4 v = *(const float4*)(base + (size_t)p * pstride + (size_t)slot * 4);
            acc.x += v.x; acc.y += v.y; acc.z += v.z; acc.w += v.w;
        }
        const int t = slot >> 4;            // token within block
        const int e = (slot & 15) * 4;      // expert quad
        *(float4*)&logits[t][e] = acc;
    }
    __syncthreads();

    // top-8 + softmax: one thread per token
    if (tid < BM) {
        const float* rowv = &logits[tid][0];
        unsigned long long used = 0ull;
        float vals[TOPK];
        int   idx[TOPK];
#pragma unroll
        for (int s = 0; s < TOPK; ++s) {
            float best = -INFINITY;
            int   bi   = 0;
            for (int e = 0; e < E_EXP; ++e) {
                if (!((used >> e) & 1ull)) {
                    float v = rowv[e];
                    if (v > best) { best = v; bi = e; }
                }
            }
            used |= 1ull << bi;
            vals[s] = best;
            idx[s]  = bi;
        }
        const float mx = vals[0];
        float ev[TOPK];
        float sum = 0.0f;
#pragma unroll
        for (int s = 0; s < TOPK; ++s) { ev[s] = expf(vals[s] - mx); sum += ev[s]; }
        const float inv = 1.0f / sum;

        const int token = row0 + tid;
        float* wout = out + (size_t)token * TOPK;
#pragma unroll
        for (int s = 0; s < TOPK; ++s) wout[s] = ev[s] * inv;

        if (out_size >= T_TOK * TOPK * 2) {
            float* eout = out + (size_t)T_TOK * TOPK + (size_t)token * TOPK;
#pragma unroll
            for (int s = 0; s < TOPK; ++s) eout[s] = (float)idx[s];
        }
    }
}

extern "C" void kernel_launch(void* const* d_in, const int* in_sizes, int n_in,
                              void* d_out, int out_size)
{
    const float* a = (const float*)d_in[0];
    const float* b = (const float*)d_in[1];
    const float* x = a;
    const float* w = b;
    if (n_in >= 2 && in_sizes[0] == D_DIM * E_EXP && in_sizes[1] == T_TOK * D_DIM) {
        x = b; w = a;
    }
    dim3 grid1(T_TOK / BM, NPANEL);
    router_panel_kernel<<<grid1, NTHR>>>(x, w);
    router_fold_kernel<<<T_TOK / BM, NTHR>>>((float*)d_out, out_size);
}

// round 16
// speedup vs baseline: 1.0211x; 1.0211x over previous
#include <cuda_runtime.h>
#include <math.h>

#define T_TOK  8192
#define D_DIM  4096
#define E_EXP  64
#define BM     64
#define BK     32
#define NTHR   512
#define TOPK   8
#define XROW   68    // 64 tokens + 4 pad (16B-aligned rows)

// packed fp32 FMA/ADD: per-half IEEE RN == two scalar ops, bitwise (proven R13/R14)
#define FMA2(acc, a, b) asm("fma.rn.f32x2 %0, %1, %2, %0;" : "+l"(acc) : "l"(a), "l"(b))
#define ADD2(acc, b)    asm("add.rn.f32x2 %0, %0, %1;"     : "+l"(acc) : "l"(b))
#define PACK2(out, v)   asm("mov.b64 %0, {%1, %1};"        : "=l"(out) : "f"(v))

__global__ __launch_bounds__(NTHR, 1)
void router_kernel(const float* __restrict__ x,   // [T, D]
                   const float* __restrict__ w,   // [D, E]
                   float* __restrict__ out,
                   int out_size)
{
    __shared__ float xs[2][BK][XROW];       // double-buffered, k-major
    __shared__ float ws[2][BK][E_EXP];
    __shared__ float logits[BM][E_EXP + 1];

    const int tid  = threadIdx.x;
    const int tx   = tid & 15;              // experts 4tx..4tx+3
    const int ty   = tid >> 4;              // tokens 2ty, 2ty+1  (ty in 0..31)
    const int row0 = blockIdx.x * BM;

    // FROZEN association: 8 contiguous 512-k panels, serial ascending FMA within
    // panel, panels folded ascending. FFMA2 halves = independent IEEE chains.
    unsigned long long tot2[2][2], cha2[2][2];
#pragma unroll
    for (int i = 0; i < 2; ++i)
#pragma unroll
        for (int p = 0; p < 2; ++p) { tot2[i][p] = 0ull; cha2[i][p] = 0ull; }

    // loaders: 512 threads, 1 float4 of x and 1 float4 of w each per chunk
    const int xm = tid >> 3, xq = tid & 7;       // token, k-quad
    const int wk = tid >> 4, weq = tid & 15;     // k-row, expert quad

    const float* xbase = x + (size_t)row0 * D_DIM;

    const int NCHUNK = D_DIM / BK;   // 128 chunks; 16 chunks = one 512-k panel

    // prologue: chunk 0 -> buf0
    float4 xr = *(const float4*)(xbase + xm * D_DIM + xq * 4);
    float4 wr = *(const float4*)(w + (size_t)wk * E_EXP + weq * 4);
    xs[0][xq * 4 + 0][xm] = xr.x;
    xs[0][xq * 4 + 1][xm] = xr.y;
    xs[0][xq * 4 + 2][xm] = xr.z;
    xs[0][xq * 4 + 3][xm] = xr.w;
    *(float4*)&ws[0][wk][weq * 4] = wr;
    __syncthreads();
    // prefetch chunk 1 into regs
    xr = *(const float4*)(xbase + xm * D_DIM + BK + xq * 4);
    wr = *(const float4*)(w + (size_t)(BK + wk) * E_EXP + weq * 4);

    for (int c = 0; c < NCHUNK; ++c) {
        const int cur = c & 1;
        // store chunk c+1 into the other buffer (parity-safe: last read at c-1,
        // which completed before the previous barrier)
        if (c + 1 < NCHUNK) {
            const int nxt = (c + 1) & 1;
            xs[nxt][xq * 4 + 0][xm] = xr.x;
            xs[nxt][xq * 4 + 1][xm] = xr.y;
            xs[nxt][xq * 4 + 2][xm] = xr.z;
            xs[nxt][xq * 4 + 3][xm] = xr.w;
            *(float4*)&ws[nxt][wk][weq * 4] = wr;
        }
        // prefetch chunk c+2 into regs
        if (c + 2 < NCHUNK) {
            const int c0 = (c + 2) * BK;
            xr = *(const float4*)(xbase + xm * D_DIM + c0 + xq * 4);
            wr = *(const float4*)(w + (size_t)(c0 + wk) * E_EXP + weq * 4);
        }

        // compute chunk c: serial ascending k; 4 FFMA2 + 2 packs per k
#pragma unroll 8
        for (int k = 0; k < BK; ++k) {
            const float2 xt = *(const float2*)&xs[cur][k][ty * 2];
            const ulonglong2 wp = *(const ulonglong2*)&ws[cur][k][tx * 4];
            unsigned long long x0, x1;
            PACK2(x0, xt.x); PACK2(x1, xt.y);
            FMA2(cha2[0][0], x0, wp.x); FMA2(cha2[0][1], x0, wp.y);
            FMA2(cha2[1][0], x1, wp.x); FMA2(cha2[1][1], x1, wp.y);
        }

        // end of a 512-k panel: fold panel sum into total (ascending), reset
        if ((c & 15) == 15) {
#pragma unroll
            for (int i = 0; i < 2; ++i)
#pragma unroll
                for (int p = 0; p < 2; ++p) {
                    ADD2(tot2[i][p], cha2[i][p]);
                    cha2[i][p] = 0ull;
                }
        }
        __syncthreads();
    }

    // unpack packed totals into logits
#pragma unroll
    for (int i = 0; i < 2; ++i)
#pragma unroll
        for (int p = 0; p < 2; ++p) {
            const unsigned long long v = tot2[i][p];
            logits[ty * 2 + i][tx * 4 + 2 * p + 0] = __uint_as_float((unsigned int)v);
            logits[ty * 2 + i][tx * 4 + 2 * p + 1] = __uint_as_float((unsigned int)(v >> 32));
        }
    __syncthreads();

    // ---- top-8 + softmax: one thread per token ----
    if (tid < BM) {
        const float* rowv = &logits[tid][0];
        unsigned long long used = 0ull;
        float vals[TOPK];
        int   idx[TOPK];
#pragma unroll
        for (int s = 0; s < TOPK; ++s) {
            float best = -INFINITY;
            int   bi   = 0;
            for (int e = 0; e < E_EXP; ++e) {
                if (!((used >> e) & 1ull)) {
                    float v = rowv[e];
                    if (v > best) { best = v; bi = e; }
                }
            }
            used |= 1ull << bi;
            vals[s] = best;
            idx[s]  = bi;
        }
        const float mx = vals[0];
        float ev[TOPK];
        float sum = 0.0f;
#pragma unroll
        for (int s = 0; s < TOPK; ++s) { ev[s] = expf(vals[s] - mx); sum += ev[s]; }
        const float inv = 1.0f / sum;

        const int token = row0 + tid;
        float* wout = out + (size_t)token * TOPK;
#pragma unroll
        for (int s = 0; s < TOPK; ++s) wout[s] = ev[s] * inv;

        if (out_size >= T_TOK * TOPK * 2) {
            float* eout = out + (size_t)T_TOK * TOPK + (size_t)token * TOPK;
#pragma unroll
            for (int s = 0; s < TOPK; ++s) eout[s] = (float)idx[s];
        }
    }
}

extern "C" void kernel_launch(void* const* d_in, const int* in_sizes, int n_in,
                              void* d_out, int out_size)
{
    const float* a = (const float*)d_in[0];
    const float* b = (const float*)d_in[1];
    const float* x = a;
    const float* w = b;
    if (n_in >= 2 && in_sizes[0] == D_DIM * E_EXP && in_sizes[1] == T_TOK * D_DIM) {
        x = b; w = a;
    }
    router_kernel<<<T_TOK / BM, NTHR>>>(x, w, (float*)d_out, out_size);
}